// round 1
// baseline (speedup 1.0000x reference)
#include <cuda_runtime.h>
#include <cuda_bf16.h>
#include <cstdint>

// ---------------------------------------------------------------------------
// GIN layer:  out = BN( MLP( x + scatter_sum(x[src] -> dst) ) ) + x
//   MLP: relu(h @ W1 + b1) @ W2 + b2
//   BN : batch (training) stats over N rows, biased var, affine gamma/beta
//
// Strategy:
//  - CSR built in-kernel (hist -> scan -> fill), per-node gather sum (no float
//    atomics; neighbor lists sorted per node for deterministic fp order).
//  - GEMMs on tensor cores with bf16 2-term split (hi/lo) for fp32-grade
//    accuracy: C = Ah*Bh + Ah*Bl + Al*Bh   (lo*lo dropped, ~2^-18 rel)
//  - BN stats via fixed-order two-stage reduction (deterministic).
// ---------------------------------------------------------------------------

#define DIM 512
#define NMAX 10000
#define EMAX 160000
#define PARTS 100

typedef __nv_bfloat16 bf16;
typedef __nv_bfloat162 bf162;

// ---- scratch (device globals; no allocations allowed) ----
__device__ int g_deg[NMAX];
__device__ int g_off[NMAX];
__device__ int g_cur[NMAX];
__device__ int g_csr[EMAX];

__device__ __align__(16) bf16 g_h0h[NMAX * DIM];
__device__ __align__(16) bf16 g_h0l[NMAX * DIM];
__device__ __align__(16) bf16 g_h1h[NMAX * DIM];
__device__ __align__(16) bf16 g_h1l[NMAX * DIM];
__device__ __align__(16) bf16 g_w1h[DIM * DIM];   // transposed: [n][k]
__device__ __align__(16) bf16 g_w1l[DIM * DIM];
__device__ __align__(16) bf16 g_w2h[DIM * DIM];
__device__ __align__(16) bf16 g_w2l[DIM * DIM];
__device__ __align__(16) float g_h2[NMAX * DIM];

__device__ __align__(16) float g_parts[PARTS][DIM];
__device__ __align__(16) float g_partq[PARTS][DIM];
__device__ __align__(16) float g_scale[DIM];
__device__ __align__(16) float g_shift[DIM];

// ---------------------------------------------------------------------------
// small helpers
// ---------------------------------------------------------------------------
__device__ __forceinline__ void split_bf16(float v, bf16& hi, bf16& lo) {
    hi = __float2bfloat16(v);
    lo = __float2bfloat16(v - __bfloat162float(hi));
}

__device__ __forceinline__ void mma_bf16(float* d, const unsigned* a, const unsigned* b) {
    asm volatile(
        "mma.sync.aligned.m16n8k16.row.col.f32.bf16.bf16.f32 "
        "{%0,%1,%2,%3}, {%4,%5,%6,%7}, {%8,%9}, {%0,%1,%2,%3};\n"
        : "+f"(d[0]), "+f"(d[1]), "+f"(d[2]), "+f"(d[3])
        : "r"(a[0]), "r"(a[1]), "r"(a[2]), "r"(a[3]), "r"(b[0]), "r"(b[1]));
}

__device__ __forceinline__ void ldsm4(unsigned* r, const void* p) {
    unsigned addr = (unsigned)__cvta_generic_to_shared(p);
    asm volatile(
        "ldmatrix.sync.aligned.m8n8.x4.shared.b16 {%0,%1,%2,%3}, [%4];\n"
        : "=r"(r[0]), "=r"(r[1]), "=r"(r[2]), "=r"(r[3])
        : "r"(addr));
}

// ---------------------------------------------------------------------------
// 1) zero degree counters
// ---------------------------------------------------------------------------
__global__ void k_zero(int n) {
    int i = blockIdx.x * blockDim.x + threadIdx.x;
    if (i < n) g_deg[i] = 0;
}

// 2) degree histogram
__global__ void k_hist(const int* __restrict__ dst, int e) {
    int i = blockIdx.x * blockDim.x + threadIdx.x;
    if (i < e) atomicAdd(&g_deg[dst[i]], 1);
}

// 3) exclusive scan of degrees (single block, 1024 threads)
__global__ void k_scan(int n) {
    __shared__ int wsum[32];
    __shared__ int s_carry;
    int tid = threadIdx.x, lane = tid & 31, w = tid >> 5;
    if (tid == 0) s_carry = 0;
    __syncthreads();
    for (int base = 0; base < n; base += 1024) {
        int idx = base + tid;
        int v = (idx < n) ? g_deg[idx] : 0;
        int xv = v;
        #pragma unroll
        for (int o = 1; o < 32; o <<= 1) {
            int y = __shfl_up_sync(0xffffffffu, xv, o);
            if (lane >= o) xv += y;
        }
        if (lane == 31) wsum[w] = xv;
        __syncthreads();
        if (w == 0) {
            int s = wsum[lane];
            #pragma unroll
            for (int o = 1; o < 32; o <<= 1) {
                int y = __shfl_up_sync(0xffffffffu, s, o);
                if (lane >= o) s += y;
            }
            wsum[lane] = s;
        }
        __syncthreads();
        int incl = xv + (w > 0 ? wsum[w - 1] : 0);
        int excl = incl - v + s_carry;
        if (idx < n) { g_off[idx] = excl; g_cur[idx] = excl; }
        int total = wsum[31];
        __syncthreads();
        if (tid == 0) s_carry += total;
        __syncthreads();
    }
}

// 4) CSR fill (slot order nondeterministic; fixed by per-node sort in k_agg)
__global__ void k_fill(const int* __restrict__ src, const int* __restrict__ dst, int e) {
    int i = blockIdx.x * blockDim.x + threadIdx.x;
    if (i < e) {
        int p = atomicAdd(&g_cur[dst[i]], 1);
        g_csr[p] = src[i];
    }
}

// 5) weight convert + transpose: W[k][n] -> Wt_hi/lo[n][k]
__global__ void k_wconv(const float* __restrict__ W1, const float* __restrict__ W2) {
    int i = blockIdx.x * blockDim.x + threadIdx.x;
    if (i >= DIM * DIM) return;
    int k = i / DIM, nn = i % DIM;
    bf16 h, l;
    split_bf16(W1[i], h, l);
    g_w1h[nn * DIM + k] = h; g_w1l[nn * DIM + k] = l;
    split_bf16(W2[i], h, l);
    g_w2h[nn * DIM + k] = h; g_w2l[nn * DIM + k] = l;
}

// 6) aggregation: h0[i] = x[i] + sum_{j in N(i)} x[j]; write bf16 hi/lo split.
//    One block (128 threads) per node; each thread owns one float4 column.
__global__ void __launch_bounds__(128) k_agg(const float* __restrict__ x, int n) {
    __shared__ int nb[1024];
    int i = blockIdx.x;
    int t = threadIdx.x;
    const float4* x4 = (const float4*)x;
    float4 acc = x4[(size_t)i * 128 + t];
    int s = g_off[i];
    int dcount = g_deg[i];

    if (dcount <= 1024) {
        for (int u = t; u < dcount; u += 128) nb[u] = g_csr[s + u];
        __syncthreads();
        if (t == 0) {  // insertion sort -> deterministic accumulation order
            for (int a = 1; a < dcount; a++) {
                int key = nb[a];
                int b = a - 1;
                while (b >= 0 && nb[b] > key) { nb[b + 1] = nb[b]; b--; }
                nb[b + 1] = key;
            }
        }
        __syncthreads();
        for (int u = 0; u < dcount; u++) {
            float4 v = x4[(size_t)nb[u] * 128 + t];
            acc.x += v.x; acc.y += v.y; acc.z += v.z; acc.w += v.w;
        }
    } else {  // fallback (not expected at avg degree 16)
        for (int base = 0; base < dcount; base += 1024) {
            int cnt = min(1024, dcount - base);
            __syncthreads();
            for (int u = t; u < cnt; u += 128) nb[u] = g_csr[s + base + u];
            __syncthreads();
            for (int u = 0; u < cnt; u++) {
                float4 v = x4[(size_t)nb[u] * 128 + t];
                acc.x += v.x; acc.y += v.y; acc.z += v.z; acc.w += v.w;
            }
        }
    }

    float f[4] = {acc.x, acc.y, acc.z, acc.w};
    bf16 hh[4], ll[4];
    #pragma unroll
    for (int q = 0; q < 4; q++) split_bf16(f[q], hh[q], ll[q]);
    size_t base = (size_t)i * DIM + (size_t)t * 4;
    bf162 h01; h01.x = hh[0]; h01.y = hh[1];
    bf162 h23; h23.x = hh[2]; h23.y = hh[3];
    bf162 l01; l01.x = ll[0]; l01.y = ll[1];
    bf162 l23; l23.x = ll[2]; l23.y = ll[3];
    *(bf162*)(g_h0h + base)     = h01;
    *(bf162*)(g_h0h + base + 2) = h23;
    *(bf162*)(g_h0l + base)     = l01;
    *(bf162*)(g_h0l + base + 2) = l23;
}

// ---------------------------------------------------------------------------
// 7/8) GEMM: C[M,512] = A[M,512] * W[512,512] (+bias), split-bf16 on tensor cores
//   EPI==1: A = h0, W = W1t, epilogue bias+relu -> g_h1 hi/lo
//   EPI==0: A = h1, W = W2t, epilogue bias      -> g_h2 fp32
//   Tiles: BM=128, BN=128, BK=32; 8 warps, warp tile 64x32.
// ---------------------------------------------------------------------------
template <int EPI>
__global__ void __launch_bounds__(256) k_gemm(const float* __restrict__ bias, int M) {
    const bf16* Ah = (EPI == 1) ? g_h0h : g_h1h;
    const bf16* Al = (EPI == 1) ? g_h0l : g_h1l;
    const bf16* Bh = (EPI == 1) ? g_w1h : g_w2h;
    const bf16* Bl = (EPI == 1) ? g_w1l : g_w2l;

    __shared__ __align__(16) unsigned short sAh[128][40];
    __shared__ __align__(16) unsigned short sAl[128][40];
    __shared__ __align__(16) unsigned short sBh[128][40];
    __shared__ __align__(16) unsigned short sBl[128][40];

    const int t = threadIdx.x;
    const int m0 = blockIdx.y * 128;
    const int n0 = blockIdx.x * 128;
    const int lr = t >> 1, seg = t & 1;
    const int lane = t & 31, wid = t >> 5;
    const int wm = (wid >> 2) * 64;   // warp row base in tile
    const int wn = (wid & 3) * 32;    // warp col base in tile

    float acc[4][4][4];
    #pragma unroll
    for (int a = 0; a < 4; a++)
        #pragma unroll
        for (int b = 0; b < 4; b++)
            #pragma unroll
            for (int c = 0; c < 4; c++) acc[a][b][c] = 0.f;

    for (int k0 = 0; k0 < 512; k0 += 32) {
        __syncthreads();
        {   // A tile (rows m0..m0+127, cols k0..k0+31) hi+lo
            int row = m0 + lr;
            uint4 v0 = {0,0,0,0}, v1 = v0, w0 = v0, w1 = v0;
            if (row < M) {
                const uint4* p = (const uint4*)(Ah + (size_t)row * 512 + k0 + seg * 16);
                v0 = p[0]; v1 = p[1];
                const uint4* q = (const uint4*)(Al + (size_t)row * 512 + k0 + seg * 16);
                w0 = q[0]; w1 = q[1];
            }
            *(uint4*)&sAh[lr][seg * 16]     = v0;
            *(uint4*)&sAh[lr][seg * 16 + 8] = v1;
            *(uint4*)&sAl[lr][seg * 16]     = w0;
            *(uint4*)&sAl[lr][seg * 16 + 8] = w1;
        }
        {   // B tile: Wt layout [n][k]; rows n0..n0+127, cols k0..k0+31
            int nrow = n0 + lr;
            const uint4* p = (const uint4*)(Bh + (size_t)nrow * 512 + k0 + seg * 16);
            uint4 v0 = p[0], v1 = p[1];
            const uint4* q = (const uint4*)(Bl + (size_t)nrow * 512 + k0 + seg * 16);
            uint4 w0 = q[0], w1 = q[1];
            *(uint4*)&sBh[lr][seg * 16]     = v0;
            *(uint4*)&sBh[lr][seg * 16 + 8] = v1;
            *(uint4*)&sBl[lr][seg * 16]     = w0;
            *(uint4*)&sBl[lr][seg * 16 + 8] = w1;
        }
        __syncthreads();

        #pragma unroll
        for (int kk = 0; kk < 32; kk += 16) {
            unsigned bh[4][2], bl[4][2];
            #pragma unroll
            for (int g = 0; g < 2; g++) {
                int nr = wn + g * 16 + (lane & 7) + ((lane & 16) ? 8 : 0);
                int kc = kk + ((lane & 8) ? 8 : 0);
                unsigned r[4];
                ldsm4(r, &sBh[nr][kc]);
                bh[g*2][0] = r[0]; bh[g*2][1] = r[1];
                bh[g*2+1][0] = r[2]; bh[g*2+1][1] = r[3];
                ldsm4(r, &sBl[nr][kc]);
                bl[g*2][0] = r[0]; bl[g*2][1] = r[1];
                bl[g*2+1][0] = r[2]; bl[g*2+1][1] = r[3];
            }
            #pragma unroll
            for (int mf = 0; mf < 4; mf++) {
                int ar = wm + mf * 16 + (lane & 15);
                int ac = kk + ((lane >> 4) << 3);
                unsigned ah[4], al[4];
                ldsm4(ah, &sAh[ar][ac]);
                ldsm4(al, &sAl[ar][ac]);
                #pragma unroll
                for (int nf = 0; nf < 4; nf++) {
                    mma_bf16(acc[mf][nf], ah, bh[nf]);
                    mma_bf16(acc[mf][nf], ah, bl[nf]);
                    mma_bf16(acc[mf][nf], al, bh[nf]);
                }
            }
        }
    }

    // epilogue
    #pragma unroll
    for (int mf = 0; mf < 4; mf++) {
        #pragma unroll
        for (int nf = 0; nf < 4; nf++) {
            int col = n0 + wn + nf * 8 + (lane & 3) * 2;
            float b0 = bias[col], b1 = bias[col + 1];
            #pragma unroll
            for (int h = 0; h < 2; h++) {
                int row = m0 + wm + mf * 16 + (lane >> 2) + h * 8;
                if (row < M) {
                    float v0 = acc[mf][nf][h * 2 + 0] + b0;
                    float v1 = acc[mf][nf][h * 2 + 1] + b1;
                    if (EPI == 1) {
                        v0 = fmaxf(v0, 0.f);
                        v1 = fmaxf(v1, 0.f);
                        bf16 h0v, l0v, h1v, l1v;
                        split_bf16(v0, h0v, l0v);
                        split_bf16(v1, h1v, l1v);
                        bf162 hv; hv.x = h0v; hv.y = h1v;
                        bf162 lv; lv.x = l0v; lv.y = l1v;
                        *(bf162*)(g_h1h + (size_t)row * 512 + col) = hv;
                        *(bf162*)(g_h1l + (size_t)row * 512 + col) = lv;
                    } else {
                        float2 fv; fv.x = v0; fv.y = v1;
                        *(float2*)(g_h2 + (size_t)row * 512 + col) = fv;
                    }
                }
            }
        }
    }
}

// 9) BN partial stats (fixed block->rows mapping, deterministic)
__global__ void k_stats(int n) {
    int t = threadIdx.x;          // 256
    int blk = blockIdx.x;         // PARTS
    int rpb = (n + PARTS - 1) / PARTS;
    int r0 = blk * rpb;
    int r1 = min(r0 + rpb, n);
    int c0 = t, c1 = t + 256;
    float s0 = 0, q0 = 0, s1 = 0, q1 = 0;
    for (int r = r0; r < r1; r++) {
        float a = g_h2[(size_t)r * DIM + c0];
        float b = g_h2[(size_t)r * DIM + c1];
        s0 += a; q0 += a * a;
        s1 += b; q1 += b * b;
    }
    g_parts[blk][c0] = s0; g_partq[blk][c0] = q0;
    g_parts[blk][c1] = s1; g_partq[blk][c1] = q1;
}

// 10) final BN params (fixed-order reduce over parts)
__global__ void k_bnparam(const float* __restrict__ gamma, const float* __restrict__ beta,
                          float invn) {
    int c = blockIdx.x * blockDim.x + threadIdx.x;
    if (c >= DIM) return;
    float s = 0, q = 0;
    for (int p = 0; p < PARTS; p++) { s += g_parts[p][c]; q += g_partq[p][c]; }
    float mean = s * invn;
    float var = q * invn - mean * mean;
    float sc = gamma[c] * rsqrtf(var + 1e-5f);
    g_scale[c] = sc;
    g_shift[c] = beta[c] - mean * sc;
}

// 11) out = h2*scale + shift + x
__global__ void k_out(const float* __restrict__ x, float* __restrict__ out, int n) {
    int i = blockIdx.x * blockDim.x + threadIdx.x;
    if (i >= n * 128) return;
    int c4 = i & 127;
    float4 h = ((const float4*)g_h2)[i];
    float4 xv = ((const float4*)x)[i];
    float4 sc = ((const float4*)g_scale)[c4];
    float4 sh = ((const float4*)g_shift)[c4];
    float4 o;
    o.x = h.x * sc.x + sh.x + xv.x;
    o.y = h.y * sc.y + sh.y + xv.y;
    o.z = h.z * sc.z + sh.z + xv.z;
    o.w = h.w * sc.w + sh.w + xv.w;
    ((float4*)out)[i] = o;
}

// ---------------------------------------------------------------------------
extern "C" void kernel_launch(void* const* d_in, const int* in_sizes, int n_in,
                              void* d_out, int out_size) {
    const float* x     = (const float*)d_in[0];
    const int*   ei    = (const int*)d_in[1];
    const float* W1    = (const float*)d_in[2];
    const float* b1    = (const float*)d_in[3];
    const float* W2    = (const float*)d_in[4];
    const float* b2    = (const float*)d_in[5];
    const float* gamma = (const float*)d_in[6];
    const float* beta  = (const float*)d_in[7];
    float* out = (float*)d_out;

    int n = in_sizes[0] / DIM;
    int e = in_sizes[1] / 2;
    const int* src = ei;
    const int* dst = ei + e;

    k_zero<<<(n + 255) / 256, 256>>>(n);
    k_hist<<<(e + 255) / 256, 256>>>(dst, e);
    k_scan<<<1, 1024>>>(n);
    k_fill<<<(e + 255) / 256, 256>>>(src, dst, e);
    k_wconv<<<(DIM * DIM + 255) / 256, 256>>>(W1, W2);
    k_agg<<<n, 128>>>(x, n);

    dim3 gg(4, (n + 127) / 128);
    k_gemm<1><<<gg, 256>>>(b1, n);
    k_gemm<0><<<gg, 256>>>(b2, n);

    k_stats<<<PARTS, 256>>>(n);
    k_bnparam<<<2, 256>>>(gamma, beta, 1.0f / (float)n);
    k_out<<<(n * 128 + 255) / 256, 256>>>(x, out, n);
}

// round 3
// speedup vs baseline: 1.1740x; 1.1740x over previous
#include <cuda_runtime.h>
#include <cuda_bf16.h>
#include <cstdint>

// ---------------------------------------------------------------------------
// GIN layer:  out = BN( MLP( x + scatter_sum(x[src] -> dst) ) ) + x
// Round 3: legacy HMMA (mma.sync) GEMMs with cp.async 3-stage pipeline,
//          bf16 2-term split accuracy (C = Ah*Bh + Ah*Bl + Al*Bh),
//          BN partial stats fused into GEMM2 epilogue.
// (tcgen05 unavailable: harness emits compute_100 PTX, not compute_100a.)
// ---------------------------------------------------------------------------

#define DIM 512
#define NMAX 10000
#define EMAX 160000
#define PARTS 80   // ceil(10000/128) = 79 used

typedef __nv_bfloat16 bf16;
typedef __nv_bfloat162 bf162;

// ---- scratch (device globals; no allocations allowed) ----
__device__ int g_deg[NMAX];
__device__ int g_off[NMAX];
__device__ int g_cur[NMAX];
__device__ int g_csr[EMAX];

__device__ __align__(16) bf16 g_h0h[NMAX * DIM];
__device__ __align__(16) bf16 g_h0l[NMAX * DIM];
__device__ __align__(16) bf16 g_h1h[NMAX * DIM];
__device__ __align__(16) bf16 g_h1l[NMAX * DIM];
__device__ __align__(16) bf16 g_w1h[DIM * DIM];   // transposed: [n][k]
__device__ __align__(16) bf16 g_w1l[DIM * DIM];
__device__ __align__(16) bf16 g_w2h[DIM * DIM];
__device__ __align__(16) bf16 g_w2l[DIM * DIM];
__device__ __align__(16) float g_h2[NMAX * DIM];

__device__ __align__(16) float g_parts[PARTS][DIM];
__device__ __align__(16) float g_partq[PARTS][DIM];
__device__ __align__(16) float g_scale[DIM];
__device__ __align__(16) float g_shift[DIM];

// ---------------------------------------------------------------------------
// helpers
// ---------------------------------------------------------------------------
__device__ __forceinline__ void split_bf16(float v, bf16& hi, bf16& lo) {
    hi = __float2bfloat16(v);
    lo = __float2bfloat16(v - __bfloat162float(hi));
}

__device__ __forceinline__ void mma_bf16(float* d, const unsigned* a, const unsigned* b) {
    asm volatile(
        "mma.sync.aligned.m16n8k16.row.col.f32.bf16.bf16.f32 "
        "{%0,%1,%2,%3}, {%4,%5,%6,%7}, {%8,%9}, {%0,%1,%2,%3};\n"
        : "+f"(d[0]), "+f"(d[1]), "+f"(d[2]), "+f"(d[3])
        : "r"(a[0]), "r"(a[1]), "r"(a[2]), "r"(a[3]), "r"(b[0]), "r"(b[1]));
}

__device__ __forceinline__ void ldsm4(unsigned* r, uint32_t saddr) {
    asm volatile(
        "ldmatrix.sync.aligned.m8n8.x4.shared.b16 {%0,%1,%2,%3}, [%4];\n"
        : "=r"(r[0]), "=r"(r[1]), "=r"(r[2]), "=r"(r[3])
        : "r"(saddr));
}

__device__ __forceinline__ void cp16(uint32_t saddr, const void* gaddr, int srcsize) {
    asm volatile("cp.async.cg.shared.global [%0], [%1], 16, %2;\n"
                 :: "r"(saddr), "l"(gaddr), "r"(srcsize));
}
__device__ __forceinline__ void cp_commit() {
    asm volatile("cp.async.commit_group;\n" ::: "memory");
}
__device__ __forceinline__ void cp_wait1() {
    asm volatile("cp.async.wait_group 1;\n" ::: "memory");
}

// ---------------------------------------------------------------------------
// graph prep kernels
// ---------------------------------------------------------------------------
__global__ void k_wconv(const float* __restrict__ W1, const float* __restrict__ W2, int n) {
    int i = blockIdx.x * blockDim.x + threadIdx.x;
    if (i < n) g_deg[i] = 0;
    if (i >= DIM * DIM) return;
    int k = i / DIM, nn = i % DIM;
    bf16 h, l;
    split_bf16(W1[i], h, l);
    g_w1h[nn * DIM + k] = h; g_w1l[nn * DIM + k] = l;
    split_bf16(W2[i], h, l);
    g_w2h[nn * DIM + k] = h; g_w2l[nn * DIM + k] = l;
}

__global__ void k_hist(const int* __restrict__ dst, int e) {
    int i = blockIdx.x * blockDim.x + threadIdx.x;
    if (i < e) atomicAdd(&g_deg[dst[i]], 1);
}

__global__ void k_scan(int n) {
    __shared__ int wsum[32];
    __shared__ int s_carry;
    int tid = threadIdx.x, lane = tid & 31, w = tid >> 5;
    if (tid == 0) s_carry = 0;
    __syncthreads();
    for (int base = 0; base < n; base += 1024) {
        int idx = base + tid;
        int v = (idx < n) ? g_deg[idx] : 0;
        int xv = v;
        #pragma unroll
        for (int o = 1; o < 32; o <<= 1) {
            int y = __shfl_up_sync(0xffffffffu, xv, o);
            if (lane >= o) xv += y;
        }
        if (lane == 31) wsum[w] = xv;
        __syncthreads();
        if (w == 0) {
            int s = wsum[lane];
            #pragma unroll
            for (int o = 1; o < 32; o <<= 1) {
                int y = __shfl_up_sync(0xffffffffu, s, o);
                if (lane >= o) s += y;
            }
            wsum[lane] = s;
        }
        __syncthreads();
        int incl = xv + (w > 0 ? wsum[w - 1] : 0);
        int excl = incl - v + s_carry;
        if (idx < n) { g_off[idx] = excl; g_cur[idx] = excl; }
        int total = wsum[31];
        __syncthreads();
        if (tid == 0) s_carry += total;
        __syncthreads();
    }
}

__global__ void k_fill(const int* __restrict__ src, const int* __restrict__ dst, int e) {
    int i = blockIdx.x * blockDim.x + threadIdx.x;
    if (i < e) {
        int p = atomicAdd(&g_cur[dst[i]], 1);
        g_csr[p] = src[i];
    }
}

// aggregation: h0[i] = x[i] + sum_{j in N(i)} x[j]; write bf16 hi/lo split
__global__ void __launch_bounds__(128) k_agg(const float* __restrict__ x, int n) {
    __shared__ int nb[1024];
    int i = blockIdx.x;
    int t = threadIdx.x;
    const float4* x4 = (const float4*)x;
    float4 acc = x4[(size_t)i * 128 + t];
    int s = g_off[i];
    int dcount = g_deg[i];

    if (dcount <= 1024) {
        for (int u = t; u < dcount; u += 128) nb[u] = g_csr[s + u];
        __syncthreads();
        if (t == 0) {  // insertion sort -> deterministic accumulation order
            for (int a = 1; a < dcount; a++) {
                int key = nb[a];
                int b = a - 1;
                while (b >= 0 && nb[b] > key) { nb[b + 1] = nb[b]; b--; }
                nb[b + 1] = key;
            }
        }
        __syncthreads();
        for (int u = 0; u < dcount; u++) {
            float4 v = x4[(size_t)nb[u] * 128 + t];
            acc.x += v.x; acc.y += v.y; acc.z += v.z; acc.w += v.w;
        }
    } else {
        for (int base = 0; base < dcount; base += 1024) {
            int cnt = min(1024, dcount - base);
            __syncthreads();
            for (int u = t; u < cnt; u += 128) nb[u] = g_csr[s + base + u];
            __syncthreads();
            for (int u = 0; u < cnt; u++) {
                float4 v = x4[(size_t)nb[u] * 128 + t];
                acc.x += v.x; acc.y += v.y; acc.z += v.z; acc.w += v.w;
            }
        }
    }

    float f[4] = {acc.x, acc.y, acc.z, acc.w};
    bf16 hh[4], ll[4];
    #pragma unroll
    for (int q = 0; q < 4; q++) split_bf16(f[q], hh[q], ll[q]);
    size_t base = (size_t)i * DIM + (size_t)t * 4;
    bf162 h01; h01.x = hh[0]; h01.y = hh[1];
    bf162 h23; h23.x = hh[2]; h23.y = hh[3];
    bf162 l01; l01.x = ll[0]; l01.y = ll[1];
    bf162 l23; l23.x = ll[2]; l23.y = ll[3];
    *(bf162*)(g_h0h + base)     = h01;
    *(bf162*)(g_h0h + base + 2) = h23;
    *(bf162*)(g_h0l + base)     = l01;
    *(bf162*)(g_h0l + base + 2) = l23;
}

// ---------------------------------------------------------------------------
// GEMM: C[M,512] = A[M,512] * W[512,512] (+bias), split-bf16 HMMA,
//   3-stage cp.async pipeline. BM=128, BN=128, BK=32; 8 warps, warp tile 64x32.
//   EPI==1: A=h0, B=W1t, epilogue bias+relu -> g_h1 hi/lo
//   EPI==0: A=h1, B=W2t, epilogue bias -> g_h2 fp32 + fused BN partial stats
// ---------------------------------------------------------------------------
#define NCHUNK 16              // 512 / BK(32)
#define ROWB 80                // bytes per smem row (40 halves, padded)
#define ARR_BYTES (128 * ROWB) // 10240
#define OFF_AH 0
#define OFF_AL ARR_BYTES
#define OFF_BH (2 * ARR_BYTES)
#define OFF_BL (3 * ARR_BYTES)
#define STAGE_BYTES (4 * ARR_BYTES)   // 40960
#define GEMM_SMEM (3 * STAGE_BYTES)   // 122880

template <int EPI>
__global__ void __launch_bounds__(256) k_gemm(const float* __restrict__ bias, int M) {
    extern __shared__ __align__(128) char sm[];

    const bf16* __restrict__ Ah = (EPI == 1) ? g_h0h : g_h1h;
    const bf16* __restrict__ Al = (EPI == 1) ? g_h0l : g_h1l;
    const bf16* __restrict__ Bh = (EPI == 1) ? g_w1h : g_w2h;
    const bf16* __restrict__ Bl = (EPI == 1) ? g_w1l : g_w2l;

    const int t = threadIdx.x;
    const int m0 = blockIdx.y * 128;
    const int n0 = blockIdx.x * 128;
    const int lr = t >> 1, seg = t & 1;         // loader row / 32B segment
    const int lane = t & 31, wid = t >> 5;
    const int wm = (wid >> 2) * 64;
    const int wn = (wid & 3) * 32;
    const uint32_t smbase = (uint32_t)__cvta_generic_to_shared(sm);

    // loader addresses (constant across chunks except global k offset)
    const int arow = m0 + lr;
    const int apred = (arow < M) ? 16 : 0;
    const uint32_t s_off = (uint32_t)(lr * ROWB + seg * 32);
    const bf16* gA_h = Ah + (size_t)arow * 512 + seg * 16;
    const bf16* gA_l = Al + (size_t)arow * 512 + seg * 16;
    const bf16* gB_h = Bh + (size_t)(n0 + lr) * 512 + seg * 16;
    const bf16* gB_l = Bl + (size_t)(n0 + lr) * 512 + seg * 16;

    #define LOAD_CHUNK(c) do {                                                \
        uint32_t _sb = smbase + ((c) % 3) * STAGE_BYTES + s_off;              \
        int _k0 = (c) * 32;                                                   \
        cp16(_sb + OFF_AH,      gA_h + _k0,     apred);                       \
        cp16(_sb + OFF_AH + 16, gA_h + _k0 + 8, apred);                       \
        cp16(_sb + OFF_AL,      gA_l + _k0,     apred);                       \
        cp16(_sb + OFF_AL + 16, gA_l + _k0 + 8, apred);                       \
        cp16(_sb + OFF_BH,      gB_h + _k0,     16);                          \
        cp16(_sb + OFF_BH + 16, gB_h + _k0 + 8, 16);                          \
        cp16(_sb + OFF_BL,      gB_l + _k0,     16);                          \
        cp16(_sb + OFF_BL + 16, gB_l + _k0 + 8, 16);                          \
    } while (0)

    float acc[4][4][4];
    #pragma unroll
    for (int a = 0; a < 4; a++)
        #pragma unroll
        for (int b = 0; b < 4; b++)
            #pragma unroll
            for (int c = 0; c < 4; c++) acc[a][b][c] = 0.f;

    LOAD_CHUNK(0); cp_commit();
    LOAD_CHUNK(1); cp_commit();

    for (int c = 0; c < NCHUNK; ++c) {
        cp_wait1();
        __syncthreads();
        if (c + 2 < NCHUNK) LOAD_CHUNK(c + 2);
        cp_commit();   // empty group when nothing issued keeps wait count valid

        const uint32_t sb = smbase + (c % 3) * STAGE_BYTES;
        #pragma unroll
        for (int kk = 0; kk < 32; kk += 16) {
            unsigned bh[4][2], bl[4][2];
            #pragma unroll
            for (int g = 0; g < 2; g++) {
                int nr = wn + g * 16 + (lane & 7) + ((lane & 16) ? 8 : 0);
                int kc = kk + ((lane & 8) ? 8 : 0);
                unsigned r[4];
                ldsm4(r, sb + OFF_BH + nr * ROWB + kc * 2);
                bh[g*2][0] = r[0]; bh[g*2][1] = r[1];
                bh[g*2+1][0] = r[2]; bh[g*2+1][1] = r[3];
                ldsm4(r, sb + OFF_BL + nr * ROWB + kc * 2);
                bl[g*2][0] = r[0]; bl[g*2][1] = r[1];
                bl[g*2+1][0] = r[2]; bl[g*2+1][1] = r[3];
            }
            #pragma unroll
            for (int mf = 0; mf < 4; mf++) {
                int ar = wm + mf * 16 + (lane & 15);
                int ac = kk + ((lane >> 4) << 3);
                unsigned ah[4], al[4];
                ldsm4(ah, sb + OFF_AH + ar * ROWB + ac * 2);
                ldsm4(al, sb + OFF_AL + ar * ROWB + ac * 2);
                #pragma unroll
                for (int nf = 0; nf < 4; nf++) {
                    mma_bf16(acc[mf][nf], ah, bh[nf]);
                    mma_bf16(acc[mf][nf], ah, bl[nf]);
                    mma_bf16(acc[mf][nf], al, bh[nf]);
                }
            }
        }
    }

    // ---- epilogue ----
    float csum[4][2], csq[4][2];
    if (EPI == 0) {
        #pragma unroll
        for (int nf = 0; nf < 4; nf++) { csum[nf][0] = csum[nf][1] = 0.f;
                                         csq[nf][0] = csq[nf][1] = 0.f; }
    }

    #pragma unroll
    for (int mf = 0; mf < 4; mf++) {
        #pragma unroll
        for (int nf = 0; nf < 4; nf++) {
            int col = n0 + wn + nf * 8 + (lane & 3) * 2;
            float b0 = bias[col], b1 = bias[col + 1];
            #pragma unroll
            for (int h = 0; h < 2; h++) {
                int row = m0 + wm + mf * 16 + (lane >> 2) + h * 8;
                if (row < M) {
                    float v0 = acc[mf][nf][h * 2 + 0] + b0;
                    float v1 = acc[mf][nf][h * 2 + 1] + b1;
                    if (EPI == 1) {
                        v0 = fmaxf(v0, 0.f);
                        v1 = fmaxf(v1, 0.f);
                        bf16 h0v, l0v, h1v, l1v;
                        split_bf16(v0, h0v, l0v);
                        split_bf16(v1, h1v, l1v);
                        bf162 hv; hv.x = h0v; hv.y = h1v;
                        bf162 lv; lv.x = l0v; lv.y = l1v;
                        *(bf162*)(g_h1h + (size_t)row * 512 + col) = hv;
                        *(bf162*)(g_h1l + (size_t)row * 512 + col) = lv;
                    } else {
                        float2 fv; fv.x = v0; fv.y = v1;
                        *(float2*)(g_h2 + (size_t)row * 512 + col) = fv;
                        csum[nf][0] += v0; csum[nf][1] += v1;
                        csq[nf][0] += v0 * v0; csq[nf][1] += v1 * v1;
                    }
                }
            }
        }
    }

    if (EPI == 0) {
        // deterministic column reduction: shfl over lanes stride 4 (fixed order),
        // then warps 0-3 stage in smem, warps 4-7 add and store.
        #pragma unroll
        for (int nf = 0; nf < 4; nf++)
            #pragma unroll
            for (int j = 0; j < 2; j++) {
                #pragma unroll
                for (int off = 16; off >= 4; off >>= 1) {
                    csum[nf][j] += __shfl_down_sync(0xffffffffu, csum[nf][j], off);
                    csq[nf][j]  += __shfl_down_sync(0xffffffffu, csq[nf][j], off);
                }
            }
        float* s_red = (float*)sm;   // reuse pipeline smem: 256 floats
        __syncthreads();
        if (wid < 4 && (lane >> 2) == 0) {
            #pragma unroll
            for (int nf = 0; nf < 4; nf++)
                #pragma unroll
                for (int j = 0; j < 2; j++) {
                    int cit = wn + nf * 8 + (lane & 3) * 2 + j;
                    s_red[cit] = csum[nf][j];
                    s_red[128 + cit] = csq[nf][j];
                }
        }
        __syncthreads();
        if (wid >= 4 && (lane >> 2) == 0) {
            #pragma unroll
            for (int nf = 0; nf < 4; nf++)
                #pragma unroll
                for (int j = 0; j < 2; j++) {
                    int cit = wn + nf * 8 + (lane & 3) * 2 + j;
                    g_parts[blockIdx.y][n0 + cit] = s_red[cit] + csum[nf][j];
                    g_partq[blockIdx.y][n0 + cit] = s_red[128 + cit] + csq[nf][j];
                }
        }
    }
    #undef LOAD_CHUNK
}

// ---------------------------------------------------------------------------
// BN params + output
// ---------------------------------------------------------------------------
__global__ void k_bnparam(const float* __restrict__ gamma, const float* __restrict__ beta,
                          float invn, int nparts) {
    int c = blockIdx.x * blockDim.x + threadIdx.x;
    if (c >= DIM) return;
    float s = 0, q = 0;
    for (int p = 0; p < nparts; p++) { s += g_parts[p][c]; q += g_partq[p][c]; }
    float mean = s * invn;
    float var = q * invn - mean * mean;
    float sc = gamma[c] * rsqrtf(var + 1e-5f);
    g_scale[c] = sc;
    g_shift[c] = beta[c] - mean * sc;
}

__global__ void k_out(const float* __restrict__ x, float* __restrict__ out, int n) {
    int i = blockIdx.x * blockDim.x + threadIdx.x;
    if (i >= n * 128) return;
    int c4 = i & 127;
    float4 h = ((const float4*)g_h2)[i];
    float4 xv = ((const float4*)x)[i];
    float4 sc = ((const float4*)g_scale)[c4];
    float4 sh = ((const float4*)g_shift)[c4];
    float4 o;
    o.x = h.x * sc.x + sh.x + xv.x;
    o.y = h.y * sc.y + sh.y + xv.y;
    o.z = h.z * sc.z + sh.z + xv.z;
    o.w = h.w * sc.w + sh.w + xv.w;
    ((float4*)out)[i] = o;
}

// ---------------------------------------------------------------------------
extern "C" void kernel_launch(void* const* d_in, const int* in_sizes, int n_in,
                              void* d_out, int out_size) {
    const float* x     = (const float*)d_in[0];
    const int*   ei    = (const int*)d_in[1];
    const float* W1    = (const float*)d_in[2];
    const float* b1    = (const float*)d_in[3];
    const float* W2    = (const float*)d_in[4];
    const float* b2    = (const float*)d_in[5];
    const float* gamma = (const float*)d_in[6];
    const float* beta  = (const float*)d_in[7];
    float* out = (float*)d_out;

    int n = in_sizes[0] / DIM;
    int e = in_sizes[1] / 2;
    const int* src = ei;
    const int* dst = ei + e;

    static bool attr_set = false;
    if (!attr_set) {
        cudaFuncSetAttribute(k_gemm<1>, cudaFuncAttributeMaxDynamicSharedMemorySize, GEMM_SMEM);
        cudaFuncSetAttribute(k_gemm<0>, cudaFuncAttributeMaxDynamicSharedMemorySize, GEMM_SMEM);
        attr_set = true;
    }

    k_wconv<<<(DIM * DIM + 255) / 256, 256>>>(W1, W2, n);
    k_hist<<<(e + 255) / 256, 256>>>(dst, e);
    k_scan<<<1, 1024>>>(n);
    k_fill<<<(e + 255) / 256, 256>>>(src, dst, e);
    k_agg<<<n, 128>>>(x, n);

    int gy = (n + 127) / 128;               // 79
    dim3 gg(4, gy);
    k_gemm<1><<<gg, 256, GEMM_SMEM>>>(b1, n);
    k_gemm<0><<<gg, 256, GEMM_SMEM>>>(b2, n);

    k_bnparam<<<2, 256>>>(gamma, beta, 1.0f / (float)n, gy);
    k_out<<<(n * 128 + 255) / 256, 256>>>(x, out, n);
}

// round 4
// speedup vs baseline: 1.6023x; 1.3648x over previous
#include <cuda_runtime.h>
#include <cuda_fp16.h>
#include <cstdint>

// ---------------------------------------------------------------------------
// GIN layer:  out = BN( MLP( x + scatter_sum(x[src] -> dst) ) ) + x
// Round 4: fp16 2-product GEMMs (A split hi/lo fp16 exact, W single fp16):
//     C = Ah*B + Al*B ;  residual = A*(W - fp16(W)) ~ 2.8e-4 rel per GEMM.
//   3-stage cp.async HMMA pipeline; BN stats fused in GEMM2 epilogue;
//   warp-bitonic neighbor sort in aggregation (deterministic fp order).
// ---------------------------------------------------------------------------

#define DIM 512
#define NMAX 10000
#define EMAX 160000
#define PARTS 80   // ceil(10000/128) = 79 used

typedef __half fp16;

// ---- scratch (device globals; no allocations allowed) ----
__device__ int g_deg[NMAX];
__device__ int g_off[NMAX];
__device__ int g_cur[NMAX];
__device__ int g_csr[EMAX];

__device__ __align__(16) fp16 g_h0h[NMAX * DIM];
__device__ __align__(16) fp16 g_h0l[NMAX * DIM];
__device__ __align__(16) fp16 g_h1h[NMAX * DIM];
__device__ __align__(16) fp16 g_h1l[NMAX * DIM];
__device__ __align__(16) fp16 g_wt1[DIM * DIM];   // transposed: [n][k]
__device__ __align__(16) fp16 g_wt2[DIM * DIM];
__device__ __align__(16) float g_h2[NMAX * DIM];

__device__ __align__(16) float g_parts[PARTS][DIM];
__device__ __align__(16) float g_partq[PARTS][DIM];
__device__ __align__(16) float g_scale[DIM];
__device__ __align__(16) float g_shift[DIM];

// ---------------------------------------------------------------------------
// helpers
// ---------------------------------------------------------------------------
__device__ __forceinline__ void split_h(float v, fp16& hi, fp16& lo) {
    hi = __float2half_rn(v);
    lo = __float2half_rn(v - __half2float(hi));
}

__device__ __forceinline__ void mma_f16(float* d, const unsigned* a, const unsigned* b) {
    asm volatile(
        "mma.sync.aligned.m16n8k16.row.col.f32.f16.f16.f32 "
        "{%0,%1,%2,%3}, {%4,%5,%6,%7}, {%8,%9}, {%0,%1,%2,%3};\n"
        : "+f"(d[0]), "+f"(d[1]), "+f"(d[2]), "+f"(d[3])
        : "r"(a[0]), "r"(a[1]), "r"(a[2]), "r"(a[3]), "r"(b[0]), "r"(b[1]));
}

__device__ __forceinline__ void ldsm4(unsigned* r, uint32_t saddr) {
    asm volatile(
        "ldmatrix.sync.aligned.m8n8.x4.shared.b16 {%0,%1,%2,%3}, [%4];\n"
        : "=r"(r[0]), "=r"(r[1]), "=r"(r[2]), "=r"(r[3])
        : "r"(saddr));
}

__device__ __forceinline__ void cp16(uint32_t saddr, const void* gaddr, int srcsize) {
    asm volatile("cp.async.cg.shared.global [%0], [%1], 16, %2;\n"
                 :: "r"(saddr), "l"(gaddr), "r"(srcsize));
}
__device__ __forceinline__ void cp_commit() {
    asm volatile("cp.async.commit_group;\n" ::: "memory");
}
__device__ __forceinline__ void cp_wait1() {
    asm volatile("cp.async.wait_group 1;\n" ::: "memory");
}

// ---------------------------------------------------------------------------
// prep kernels
// ---------------------------------------------------------------------------
// weight convert (fp16, transposed) + zero deg
__global__ void k_wconv(const float* __restrict__ W1, const float* __restrict__ W2, int n) {
    int i = blockIdx.x * blockDim.x + threadIdx.x;
    if (i < n) g_deg[i] = 0;
    if (i >= DIM * DIM) return;
    int k = i / DIM, nn = i % DIM;
    g_wt1[nn * DIM + k] = __float2half_rn(W1[i]);
    g_wt2[nn * DIM + k] = __float2half_rn(W2[i]);
}

__global__ void k_hist(const int* __restrict__ dst, int e) {
    int i = blockIdx.x * blockDim.x + threadIdx.x;
    if (i < e) atomicAdd(&g_deg[dst[i]], 1);
}

__global__ void k_scan(int n) {
    __shared__ int wsum[32];
    __shared__ int s_carry;
    int tid = threadIdx.x, lane = tid & 31, w = tid >> 5;
    if (tid == 0) s_carry = 0;
    __syncthreads();
    for (int base = 0; base < n; base += 1024) {
        int idx = base + tid;
        int v = (idx < n) ? g_deg[idx] : 0;
        int xv = v;
        #pragma unroll
        for (int o = 1; o < 32; o <<= 1) {
            int y = __shfl_up_sync(0xffffffffu, xv, o);
            if (lane >= o) xv += y;
        }
        if (lane == 31) wsum[w] = xv;
        __syncthreads();
        if (w == 0) {
            int s = wsum[lane];
            #pragma unroll
            for (int o = 1; o < 32; o <<= 1) {
                int y = __shfl_up_sync(0xffffffffu, s, o);
                if (lane >= o) s += y;
            }
            wsum[lane] = s;
        }
        __syncthreads();
        int incl = xv + (w > 0 ? wsum[w - 1] : 0);
        int excl = incl - v + s_carry;
        if (idx < n) { g_off[idx] = excl; g_cur[idx] = excl; }
        int total = wsum[31];
        __syncthreads();
        if (tid == 0) s_carry += total;
        __syncthreads();
    }
}

__global__ void k_fill(const int* __restrict__ src, const int* __restrict__ dst, int e) {
    int i = blockIdx.x * blockDim.x + threadIdx.x;
    if (i < e) {
        int p = atomicAdd(&g_cur[dst[i]], 1);
        g_csr[p] = src[i];
    }
}

// aggregation: h0[i] = x[i] + sum_{j in N(i)} x[j]; write fp16 hi/lo split
__global__ void __launch_bounds__(128) k_agg(const float* __restrict__ x, int n) {
    __shared__ int nb[1024];
    int i = blockIdx.x;
    int t = threadIdx.x;
    const float4* x4 = (const float4*)x;
    float4 acc = x4[(size_t)i * 128 + t];
    int s = g_off[i];
    int dcount = g_deg[i];

    if (dcount <= 1024) {
        for (int u = t; u < dcount; u += 128) nb[u] = g_csr[s + u];
        __syncthreads();
        if (dcount <= 32) {
            // warp-wide bitonic sort (ascending) -> deterministic order
            if (t < 32) {
                int v = (t < dcount) ? nb[t] : 0x7fffffff;
                #pragma unroll
                for (int k = 2; k <= 32; k <<= 1) {
                    #pragma unroll
                    for (int j = k >> 1; j > 0; j >>= 1) {
                        int p = __shfl_xor_sync(0xffffffffu, v, j);
                        bool up = ((t & k) == 0);
                        bool takemin = (((t & j) == 0) == up);
                        v = takemin ? min(v, p) : max(v, p);
                    }
                }
                if (t < dcount) nb[t] = v;
            }
        } else if (t == 0) {  // rare tail: serial insertion sort
            for (int a = 1; a < dcount; a++) {
                int key = nb[a];
                int b = a - 1;
                while (b >= 0 && nb[b] > key) { nb[b + 1] = nb[b]; b--; }
                nb[b + 1] = key;
            }
        }
        __syncthreads();
        for (int u = 0; u < dcount; u++) {
            float4 v = x4[(size_t)nb[u] * 128 + t];
            acc.x += v.x; acc.y += v.y; acc.z += v.z; acc.w += v.w;
        }
    } else {
        for (int base = 0; base < dcount; base += 1024) {
            int cnt = min(1024, dcount - base);
            __syncthreads();
            for (int u = t; u < cnt; u += 128) nb[u] = g_csr[s + base + u];
            __syncthreads();
            for (int u = 0; u < cnt; u++) {
                float4 v = x4[(size_t)nb[u] * 128 + t];
                acc.x += v.x; acc.y += v.y; acc.z += v.z; acc.w += v.w;
            }
        }
    }

    float f[4] = {acc.x, acc.y, acc.z, acc.w};
    fp16 hh[4], ll[4];
    #pragma unroll
    for (int q = 0; q < 4; q++) split_h(f[q], hh[q], ll[q]);
    size_t base = (size_t)i * DIM + (size_t)t * 4;
    __half2 h01 = __halves2half2(hh[0], hh[1]);
    __half2 h23 = __halves2half2(hh[2], hh[3]);
    __half2 l01 = __halves2half2(ll[0], ll[1]);
    __half2 l23 = __halves2half2(ll[2], ll[3]);
    *(__half2*)(g_h0h + base)     = h01;
    *(__half2*)(g_h0h + base + 2) = h23;
    *(__half2*)(g_h0l + base)     = l01;
    *(__half2*)(g_h0l + base + 2) = l23;
}

// ---------------------------------------------------------------------------
// GEMM: C[M,512] = A[M,512] * W[512,512] (+bias), fp16 2-product HMMA,
//   3-stage cp.async pipeline. BM=128, BN=128, BK=32; 8 warps, warp tile 64x32.
//   EPI==1: A=h0 (hi/lo), B=wt1, epilogue bias+relu -> g_h1 hi/lo
//   EPI==0: A=h1 (hi/lo), B=wt2, epilogue bias -> g_h2 fp32 + fused BN stats
// ---------------------------------------------------------------------------
#define NCHUNK 16              // 512 / BK(32)
#define ROWB 80                // bytes per smem row (64B data + 16B pad)
#define ARR_BYTES (128 * ROWB) // 10240
#define OFF_AH 0
#define OFF_AL ARR_BYTES
#define OFF_B  (2 * ARR_BYTES)
#define STAGE_BYTES (3 * ARR_BYTES)   // 30720
#define GEMM_SMEM (3 * STAGE_BYTES)   // 92160

template <int EPI>
__global__ void __launch_bounds__(256) k_gemm(const float* __restrict__ bias, int M) {
    extern __shared__ __align__(128) char sm[];

    const fp16* __restrict__ Ah = (EPI == 1) ? g_h0h : g_h1h;
    const fp16* __restrict__ Al = (EPI == 1) ? g_h0l : g_h1l;
    const fp16* __restrict__ B  = (EPI == 1) ? g_wt1 : g_wt2;

    const int t = threadIdx.x;
    const int m0 = blockIdx.y * 128;
    const int n0 = blockIdx.x * 128;
    const int lr = t >> 1, seg = t & 1;
    const int lane = t & 31, wid = t >> 5;
    const int wm = (wid >> 2) * 64;
    const int wn = (wid & 3) * 32;
    const uint32_t smbase = (uint32_t)__cvta_generic_to_shared(sm);

    const int arow = m0 + lr;
    const int apred = (arow < M) ? 16 : 0;
    const uint32_t s_off = (uint32_t)(lr * ROWB + seg * 32);
    const fp16* gA_h = Ah + (size_t)arow * 512 + seg * 16;
    const fp16* gA_l = Al + (size_t)arow * 512 + seg * 16;
    const fp16* gB   = B + (size_t)(n0 + lr) * 512 + seg * 16;

    #define LOAD_CHUNK(c) do {                                                \
        uint32_t _sb = smbase + ((c) % 3) * STAGE_BYTES + s_off;              \
        int _k0 = (c) * 32;                                                   \
        cp16(_sb + OFF_AH,      gA_h + _k0,     apred);                       \
        cp16(_sb + OFF_AH + 16, gA_h + _k0 + 8, apred);                       \
        cp16(_sb + OFF_AL,      gA_l + _k0,     apred);                       \
        cp16(_sb + OFF_AL + 16, gA_l + _k0 + 8, apred);                       \
        cp16(_sb + OFF_B,       gB + _k0,       16);                          \
        cp16(_sb + OFF_B + 16,  gB + _k0 + 8,   16);                          \
    } while (0)

    float acc[4][4][4];
    #pragma unroll
    for (int a = 0; a < 4; a++)
        #pragma unroll
        for (int b = 0; b < 4; b++)
            #pragma unroll
            for (int c = 0; c < 4; c++) acc[a][b][c] = 0.f;

    LOAD_CHUNK(0); cp_commit();
    LOAD_CHUNK(1); cp_commit();

    for (int c = 0; c < NCHUNK; ++c) {
        cp_wait1();
        __syncthreads();
        if (c + 2 < NCHUNK) LOAD_CHUNK(c + 2);
        cp_commit();

        const uint32_t sb = smbase + (c % 3) * STAGE_BYTES;
        #pragma unroll
        for (int kk = 0; kk < 32; kk += 16) {
            unsigned bfr[4][2];
            #pragma unroll
            for (int g = 0; g < 2; g++) {
                int nr = wn + g * 16 + (lane & 7) + ((lane & 16) ? 8 : 0);
                int kc = kk + ((lane & 8) ? 8 : 0);
                unsigned r[4];
                ldsm4(r, sb + OFF_B + nr * ROWB + kc * 2);
                bfr[g*2][0] = r[0]; bfr[g*2][1] = r[1];
                bfr[g*2+1][0] = r[2]; bfr[g*2+1][1] = r[3];
            }
            #pragma unroll
            for (int mf = 0; mf < 4; mf++) {
                int ar = wm + mf * 16 + (lane & 15);
                int ac = kk + ((lane >> 4) << 3);
                unsigned ah[4], al[4];
                ldsm4(ah, sb + OFF_AH + ar * ROWB + ac * 2);
                ldsm4(al, sb + OFF_AL + ar * ROWB + ac * 2);
                #pragma unroll
                for (int nf = 0; nf < 4; nf++) {
                    mma_f16(acc[mf][nf], ah, bfr[nf]);
                    mma_f16(acc[mf][nf], al, bfr[nf]);
                }
            }
        }
    }

    // ---- epilogue ----
    float csum[4][2], csq[4][2];
    if (EPI == 0) {
        #pragma unroll
        for (int nf = 0; nf < 4; nf++) { csum[nf][0] = csum[nf][1] = 0.f;
                                         csq[nf][0] = csq[nf][1] = 0.f; }
    }

    #pragma unroll
    for (int mf = 0; mf < 4; mf++) {
        #pragma unroll
        for (int nf = 0; nf < 4; nf++) {
            int col = n0 + wn + nf * 8 + (lane & 3) * 2;
            float b0 = bias[col], b1 = bias[col + 1];
            #pragma unroll
            for (int h = 0; h < 2; h++) {
                int row = m0 + wm + mf * 16 + (lane >> 2) + h * 8;
                if (row < M) {
                    float v0 = acc[mf][nf][h * 2 + 0] + b0;
                    float v1 = acc[mf][nf][h * 2 + 1] + b1;
                    if (EPI == 1) {
                        v0 = fmaxf(v0, 0.f);
                        v1 = fmaxf(v1, 0.f);
                        fp16 h0v, l0v, h1v, l1v;
                        split_h(v0, h0v, l0v);
                        split_h(v1, h1v, l1v);
                        __half2 hv = __halves2half2(h0v, h1v);
                        __half2 lv = __halves2half2(l0v, l1v);
                        *(__half2*)(g_h1h + (size_t)row * 512 + col) = hv;
                        *(__half2*)(g_h1l + (size_t)row * 512 + col) = lv;
                    } else {
                        float2 fv; fv.x = v0; fv.y = v1;
                        *(float2*)(g_h2 + (size_t)row * 512 + col) = fv;
                        csum[nf][0] += v0; csum[nf][1] += v1;
                        csq[nf][0] += v0 * v0; csq[nf][1] += v1 * v1;
                    }
                }
            }
        }
    }

    if (EPI == 0) {
        // deterministic column reduction: shfl stride 16..4, then 2-step smem
        #pragma unroll
        for (int nf = 0; nf < 4; nf++)
            #pragma unroll
            for (int j = 0; j < 2; j++) {
                #pragma unroll
                for (int off = 16; off >= 4; off >>= 1) {
                    csum[nf][j] += __shfl_down_sync(0xffffffffu, csum[nf][j], off);
                    csq[nf][j]  += __shfl_down_sync(0xffffffffu, csq[nf][j], off);
                }
            }
        float* s_red = (float*)sm;
        __syncthreads();
        if (wid < 4 && (lane >> 2) == 0) {
            #pragma unroll
            for (int nf = 0; nf < 4; nf++)
                #pragma unroll
                for (int j = 0; j < 2; j++) {
                    int cit = wn + nf * 8 + (lane & 3) * 2 + j;
                    s_red[cit] = csum[nf][j];
                    s_red[128 + cit] = csq[nf][j];
                }
        }
        __syncthreads();
        if (wid >= 4 && (lane >> 2) == 0) {
            #pragma unroll
            for (int nf = 0; nf < 4; nf++)
                #pragma unroll
                for (int j = 0; j < 2; j++) {
                    int cit = wn + nf * 8 + (lane & 3) * 2 + j;
                    g_parts[blockIdx.y][n0 + cit] = s_red[cit] + csum[nf][j];
                    g_partq[blockIdx.y][n0 + cit] = s_red[128 + cit] + csq[nf][j];
                }
        }
    }
    #undef LOAD_CHUNK
}

// ---------------------------------------------------------------------------
// BN params + output
// ---------------------------------------------------------------------------
__global__ void k_bnparam(const float* __restrict__ gamma, const float* __restrict__ beta,
                          float invn, int nparts) {
    int c = blockIdx.x * blockDim.x + threadIdx.x;
    if (c >= DIM) return;
    float s = 0, q = 0;
    for (int p = 0; p < nparts; p++) { s += g_parts[p][c]; q += g_partq[p][c]; }
    float mean = s * invn;
    float var = q * invn - mean * mean;
    float sc = gamma[c] * rsqrtf(var + 1e-5f);
    g_scale[c] = sc;
    g_shift[c] = beta[c] - mean * sc;
}

__global__ void k_out(const float* __restrict__ x, float* __restrict__ out, int n) {
    int i = blockIdx.x * blockDim.x + threadIdx.x;
    if (i >= n * 128) return;
    int c4 = i & 127;
    float4 h = ((const float4*)g_h2)[i];
    float4 xv = ((const float4*)x)[i];
    float4 sc = ((const float4*)g_scale)[c4];
    float4 sh = ((const float4*)g_shift)[c4];
    float4 o;
    o.x = h.x * sc.x + sh.x + xv.x;
    o.y = h.y * sc.y + sh.y + xv.y;
    o.z = h.z * sc.z + sh.z + xv.z;
    o.w = h.w * sc.w + sh.w + xv.w;
    ((float4*)out)[i] = o;
}

// ---------------------------------------------------------------------------
extern "C" void kernel_launch(void* const* d_in, const int* in_sizes, int n_in,
                              void* d_out, int out_size) {
    const float* x     = (const float*)d_in[0];
    const int*   ei    = (const int*)d_in[1];
    const float* W1    = (const float*)d_in[2];
    const float* b1    = (const float*)d_in[3];
    const float* W2    = (const float*)d_in[4];
    const float* b2    = (const float*)d_in[5];
    const float* gamma = (const float*)d_in[6];
    const float* beta  = (const float*)d_in[7];
    float* out = (float*)d_out;

    int n = in_sizes[0] / DIM;
    int e = in_sizes[1] / 2;
    const int* src = ei;
    const int* dst = ei + e;

    static bool attr_set = false;
    if (!attr_set) {
        cudaFuncSetAttribute(k_gemm<1>, cudaFuncAttributeMaxDynamicSharedMemorySize, GEMM_SMEM);
        cudaFuncSetAttribute(k_gemm<0>, cudaFuncAttributeMaxDynamicSharedMemorySize, GEMM_SMEM);
        attr_set = true;
    }

    k_wconv<<<(DIM * DIM + 255) / 256, 256>>>(W1, W2, n);
    k_hist<<<(e + 255) / 256, 256>>>(dst, e);
    k_scan<<<1, 1024>>>(n);
    k_fill<<<(e + 255) / 256, 256>>>(src, dst, e);
    k_agg<<<n, 128>>>(x, n);

    int gy = (n + 127) / 128;               // 79
    dim3 gg(4, gy);
    k_gemm<1><<<gg, 256, GEMM_SMEM>>>(b1, n);
    k_gemm<0><<<gg, 256, GEMM_SMEM>>>(b2, n);

    k_bnparam<<<2, 256>>>(gamma, beta, 1.0f / (float)n, gy);
    k_out<<<(n * 128 + 255) / 256, 256>>>(x, out, n);
}

// round 5
// speedup vs baseline: 2.0988x; 1.3099x over previous
#include <cuda_runtime.h>
#include <cuda_fp16.h>
#include <cstdint>

// ---------------------------------------------------------------------------
// GIN layer:  out = BN( MLP( x + scatter_sum(x[src] -> dst) ) ) + x
// Round 5: plain fp16 HMMA GEMMs (fp32 accumulate), 1 product each.
//   Error sources: W1,W2,h0,h1 fp16 rounding -> predicted rel_err ~3.2e-4.
//   4-stage cp.async pipeline; BN stats fused in GEMM2 epilogue;
//   deterministic everywhere (sorted neighbor order, fixed reductions).
// ---------------------------------------------------------------------------

#define DIM 512
#define NMAX 10000
#define EMAX 160000
#define PARTS 80   // ceil(10000/128) = 79 used

typedef __half fp16;

// ---- scratch (device globals; no allocations allowed) ----
__device__ int g_deg[NMAX];
__device__ int g_off[NMAX];
__device__ int g_cur[NMAX];
__device__ int g_csr[EMAX];

__device__ __align__(16) fp16 g_h0[NMAX * DIM];
__device__ __align__(16) fp16 g_h1[NMAX * DIM];
__device__ __align__(16) fp16 g_wt1[DIM * DIM];   // transposed: [n][k]
__device__ __align__(16) fp16 g_wt2[DIM * DIM];
__device__ __align__(16) float g_h2[NMAX * DIM];

__device__ __align__(16) float g_parts[PARTS][DIM];
__device__ __align__(16) float g_partq[PARTS][DIM];
__device__ __align__(16) float g_scale[DIM];
__device__ __align__(16) float g_shift[DIM];

// ---------------------------------------------------------------------------
// helpers
// ---------------------------------------------------------------------------
__device__ __forceinline__ void mma_f16(float* d, const unsigned* a, const unsigned* b) {
    asm volatile(
        "mma.sync.aligned.m16n8k16.row.col.f32.f16.f16.f32 "
        "{%0,%1,%2,%3}, {%4,%5,%6,%7}, {%8,%9}, {%0,%1,%2,%3};\n"
        : "+f"(d[0]), "+f"(d[1]), "+f"(d[2]), "+f"(d[3])
        : "r"(a[0]), "r"(a[1]), "r"(a[2]), "r"(a[3]), "r"(b[0]), "r"(b[1]));
}

__device__ __forceinline__ void ldsm4(unsigned* r, uint32_t saddr) {
    asm volatile(
        "ldmatrix.sync.aligned.m8n8.x4.shared.b16 {%0,%1,%2,%3}, [%4];\n"
        : "=r"(r[0]), "=r"(r[1]), "=r"(r[2]), "=r"(r[3])
        : "r"(saddr));
}

__device__ __forceinline__ void cp16(uint32_t saddr, const void* gaddr, int srcsize) {
    asm volatile("cp.async.cg.shared.global [%0], [%1], 16, %2;\n"
                 :: "r"(saddr), "l"(gaddr), "r"(srcsize));
}
__device__ __forceinline__ void cp_commit() {
    asm volatile("cp.async.commit_group;\n" ::: "memory");
}
__device__ __forceinline__ void cp_wait2() {
    asm volatile("cp.async.wait_group 2;\n" ::: "memory");
}

// ---------------------------------------------------------------------------
// prep kernels
// ---------------------------------------------------------------------------
// weight convert (fp16, transposed) + zero deg
__global__ void k_wconv(const float* __restrict__ W1, const float* __restrict__ W2, int n) {
    int i = blockIdx.x * blockDim.x + threadIdx.x;
    if (i < n) g_deg[i] = 0;
    if (i >= DIM * DIM) return;
    int k = i / DIM, nn = i % DIM;
    g_wt1[nn * DIM + k] = __float2half_rn(W1[i]);
    g_wt2[nn * DIM + k] = __float2half_rn(W2[i]);
}

__global__ void k_hist(const int* __restrict__ dst, int e) {
    int i = blockIdx.x * blockDim.x + threadIdx.x;
    if (i < e) atomicAdd(&g_deg[dst[i]], 1);
}

__global__ void k_scan(int n) {
    __shared__ int wsum[32];
    __shared__ int s_carry;
    int tid = threadIdx.x, lane = tid & 31, w = tid >> 5;
    if (tid == 0) s_carry = 0;
    __syncthreads();
    for (int base = 0; base < n; base += 1024) {
        int idx = base + tid;
        int v = (idx < n) ? g_deg[idx] : 0;
        int xv = v;
        #pragma unroll
        for (int o = 1; o < 32; o <<= 1) {
            int y = __shfl_up_sync(0xffffffffu, xv, o);
            if (lane >= o) xv += y;
        }
        if (lane == 31) wsum[w] = xv;
        __syncthreads();
        if (w == 0) {
            int s = wsum[lane];
            #pragma unroll
            for (int o = 1; o < 32; o <<= 1) {
                int y = __shfl_up_sync(0xffffffffu, s, o);
                if (lane >= o) s += y;
            }
            wsum[lane] = s;
        }
        __syncthreads();
        int incl = xv + (w > 0 ? wsum[w - 1] : 0);
        int excl = incl - v + s_carry;
        if (idx < n) { g_off[idx] = excl; g_cur[idx] = excl; }
        int total = wsum[31];
        __syncthreads();
        if (tid == 0) s_carry += total;
        __syncthreads();
    }
}

__global__ void k_fill(const int* __restrict__ src, const int* __restrict__ dst, int e) {
    int i = blockIdx.x * blockDim.x + threadIdx.x;
    if (i < e) {
        int p = atomicAdd(&g_cur[dst[i]], 1);
        g_csr[p] = src[i];
    }
}

// aggregation: h0[i] = fp16( x[i] + sum_{j in N(i)} x[j] )
__global__ void __launch_bounds__(128) k_agg(const float* __restrict__ x, int n) {
    __shared__ int nb[1024];
    int i = blockIdx.x;
    int t = threadIdx.x;
    const float4* x4 = (const float4*)x;
    float4 acc = x4[(size_t)i * 128 + t];
    int s = g_off[i];
    int dcount = g_deg[i];

    if (dcount <= 1024) {
        for (int u = t; u < dcount; u += 128) nb[u] = g_csr[s + u];
        __syncthreads();
        if (dcount <= 32) {
            // warp-wide bitonic sort (ascending) -> deterministic order
            if (t < 32) {
                int v = (t < dcount) ? nb[t] : 0x7fffffff;
                #pragma unroll
                for (int k = 2; k <= 32; k <<= 1) {
                    #pragma unroll
                    for (int j = k >> 1; j > 0; j >>= 1) {
                        int p = __shfl_xor_sync(0xffffffffu, v, j);
                        bool up = ((t & k) == 0);
                        bool takemin = (((t & j) == 0) == up);
                        v = takemin ? min(v, p) : max(v, p);
                    }
                }
                if (t < dcount) nb[t] = v;
            }
        } else if (t == 0) {  // rare tail: serial insertion sort
            for (int a = 1; a < dcount; a++) {
                int key = nb[a];
                int b = a - 1;
                while (b >= 0 && nb[b] > key) { nb[b + 1] = nb[b]; b--; }
                nb[b + 1] = key;
            }
        }
        __syncthreads();
        for (int u = 0; u < dcount; u++) {
            float4 v = x4[(size_t)nb[u] * 128 + t];
            acc.x += v.x; acc.y += v.y; acc.z += v.z; acc.w += v.w;
        }
    } else {
        for (int base = 0; base < dcount; base += 1024) {
            int cnt = min(1024, dcount - base);
            __syncthreads();
            for (int u = t; u < cnt; u += 128) nb[u] = g_csr[s + base + u];
            __syncthreads();
            for (int u = 0; u < cnt; u++) {
                float4 v = x4[(size_t)nb[u] * 128 + t];
                acc.x += v.x; acc.y += v.y; acc.z += v.z; acc.w += v.w;
            }
        }
    }

    size_t base = (size_t)i * DIM + (size_t)t * 4;
    __half2 h01 = __halves2half2(__float2half_rn(acc.x), __float2half_rn(acc.y));
    __half2 h23 = __halves2half2(__float2half_rn(acc.z), __float2half_rn(acc.w));
    *(__half2*)(g_h0 + base)     = h01;
    *(__half2*)(g_h0 + base + 2) = h23;
}

// ---------------------------------------------------------------------------
// GEMM: C[M,512] = A[M,512] * W[512,512] (+bias), fp16 HMMA, fp32 accum.
//   4-stage cp.async pipeline. BM=128, BN=128, BK=32; 8 warps, warp tile 64x32.
//   EPI==1: A=h0, B=wt1, epilogue bias+relu -> g_h1 (fp16)
//   EPI==0: A=h1, B=wt2, epilogue bias -> g_h2 fp32 + fused BN partial stats
// ---------------------------------------------------------------------------
#define NCHUNK 16              // 512 / BK(32)
#define ROWB 80                // bytes per smem row (64B data + 16B pad)
#define ARR_BYTES (128 * ROWB) // 10240
#define OFF_A 0
#define OFF_B ARR_BYTES
#define STAGE_BYTES (2 * ARR_BYTES)   // 20480
#define GEMM_SMEM (4 * STAGE_BYTES)   // 81920

template <int EPI>
__global__ void __launch_bounds__(256) k_gemm(const float* __restrict__ bias, int M) {
    extern __shared__ __align__(128) char sm[];

    const fp16* __restrict__ A = (EPI == 1) ? g_h0 : g_h1;
    const fp16* __restrict__ B = (EPI == 1) ? g_wt1 : g_wt2;

    const int t = threadIdx.x;
    const int m0 = blockIdx.y * 128;
    const int n0 = blockIdx.x * 128;
    const int lr = t >> 1, seg = t & 1;
    const int lane = t & 31, wid = t >> 5;
    const int wm = (wid >> 2) * 64;
    const int wn = (wid & 3) * 32;
    const uint32_t smbase = (uint32_t)__cvta_generic_to_shared(sm);

    const int arow = m0 + lr;
    const int apred = (arow < M) ? 16 : 0;
    const uint32_t s_off = (uint32_t)(lr * ROWB + seg * 32);
    const fp16* gA = A + (size_t)arow * 512 + seg * 16;
    const fp16* gB = B + (size_t)(n0 + lr) * 512 + seg * 16;

    #define LOAD_CHUNK(c) do {                                                \
        uint32_t _sb = smbase + ((c) & 3) * STAGE_BYTES + s_off;              \
        int _k0 = (c) * 32;                                                   \
        cp16(_sb + OFF_A,      gA + _k0,     apred);                          \
        cp16(_sb + OFF_A + 16, gA + _k0 + 8, apred);                          \
        cp16(_sb + OFF_B,      gB + _k0,     16);                             \
        cp16(_sb + OFF_B + 16, gB + _k0 + 8, 16);                             \
    } while (0)

    float acc[4][4][4];
    #pragma unroll
    for (int a = 0; a < 4; a++)
        #pragma unroll
        for (int b = 0; b < 4; b++)
            #pragma unroll
            for (int c = 0; c < 4; c++) acc[a][b][c] = 0.f;

    LOAD_CHUNK(0); cp_commit();
    LOAD_CHUNK(1); cp_commit();
    LOAD_CHUNK(2); cp_commit();

    for (int c = 0; c < NCHUNK; ++c) {
        cp_wait2();
        __syncthreads();
        if (c + 3 < NCHUNK) LOAD_CHUNK(c + 3);
        cp_commit();

        const uint32_t sb = smbase + (c & 3) * STAGE_BYTES;
        #pragma unroll
        for (int kk = 0; kk < 32; kk += 16) {
            unsigned bfr[4][2];
            #pragma unroll
            for (int g = 0; g < 2; g++) {
                int nr = wn + g * 16 + (lane & 7) + ((lane & 16) ? 8 : 0);
                int kc = kk + ((lane & 8) ? 8 : 0);
                unsigned r[4];
                ldsm4(r, sb + OFF_B + nr * ROWB + kc * 2);
                bfr[g*2][0] = r[0]; bfr[g*2][1] = r[1];
                bfr[g*2+1][0] = r[2]; bfr[g*2+1][1] = r[3];
            }
            #pragma unroll
            for (int mf = 0; mf < 4; mf++) {
                int ar = wm + mf * 16 + (lane & 15);
                int ac = kk + ((lane >> 4) << 3);
                unsigned ah[4];
                ldsm4(ah, sb + OFF_A + ar * ROWB + ac * 2);
                #pragma unroll
                for (int nf = 0; nf < 4; nf++) {
                    mma_f16(acc[mf][nf], ah, bfr[nf]);
                }
            }
        }
    }

    // ---- epilogue ----
    float csum[4][2], csq[4][2];
    if (EPI == 0) {
        #pragma unroll
        for (int nf = 0; nf < 4; nf++) { csum[nf][0] = csum[nf][1] = 0.f;
                                         csq[nf][0] = csq[nf][1] = 0.f; }
    }

    #pragma unroll
    for (int mf = 0; mf < 4; mf++) {
        #pragma unroll
        for (int nf = 0; nf < 4; nf++) {
            int col = n0 + wn + nf * 8 + (lane & 3) * 2;
            float b0 = bias[col], b1 = bias[col + 1];
            #pragma unroll
            for (int h = 0; h < 2; h++) {
                int row = m0 + wm + mf * 16 + (lane >> 2) + h * 8;
                if (row < M) {
                    float v0 = acc[mf][nf][h * 2 + 0] + b0;
                    float v1 = acc[mf][nf][h * 2 + 1] + b1;
                    if (EPI == 1) {
                        v0 = fmaxf(v0, 0.f);
                        v1 = fmaxf(v1, 0.f);
                        __half2 hv = __halves2half2(__float2half_rn(v0),
                                                    __float2half_rn(v1));
                        *(__half2*)(g_h1 + (size_t)row * 512 + col) = hv;
                    } else {
                        float2 fv; fv.x = v0; fv.y = v1;
                        *(float2*)(g_h2 + (size_t)row * 512 + col) = fv;
                        csum[nf][0] += v0; csum[nf][1] += v1;
                        csq[nf][0] += v0 * v0; csq[nf][1] += v1 * v1;
                    }
                }
            }
        }
    }

    if (EPI == 0) {
        // deterministic column reduction: shfl stride 16..4, then 2-step smem
        #pragma unroll
        for (int nf = 0; nf < 4; nf++)
            #pragma unroll
            for (int j = 0; j < 2; j++) {
                #pragma unroll
                for (int off = 16; off >= 4; off >>= 1) {
                    csum[nf][j] += __shfl_down_sync(0xffffffffu, csum[nf][j], off);
                    csq[nf][j]  += __shfl_down_sync(0xffffffffu, csq[nf][j], off);
                }
            }
        float* s_red = (float*)sm;
        __syncthreads();
        if (wid < 4 && (lane >> 2) == 0) {
            #pragma unroll
            for (int nf = 0; nf < 4; nf++)
                #pragma unroll
                for (int j = 0; j < 2; j++) {
                    int cit = wn + nf * 8 + (lane & 3) * 2 + j;
                    s_red[cit] = csum[nf][j];
                    s_red[128 + cit] = csq[nf][j];
                }
        }
        __syncthreads();
        if (wid >= 4 && (lane >> 2) == 0) {
            #pragma unroll
            for (int nf = 0; nf < 4; nf++)
                #pragma unroll
                for (int j = 0; j < 2; j++) {
                    int cit = wn + nf * 8 + (lane & 3) * 2 + j;
                    g_parts[blockIdx.y][n0 + cit] = s_red[cit] + csum[nf][j];
                    g_partq[blockIdx.y][n0 + cit] = s_red[128 + cit] + csq[nf][j];
                }
        }
    }
    #undef LOAD_CHUNK
}

// ---------------------------------------------------------------------------
// BN params + output
// ---------------------------------------------------------------------------
__global__ void k_bnparam(const float* __restrict__ gamma, const float* __restrict__ beta,
                          float invn, int nparts) {
    int c = blockIdx.x * blockDim.x + threadIdx.x;
    if (c >= DIM) return;
    float s = 0, q = 0;
    for (int p = 0; p < nparts; p++) { s += g_parts[p][c]; q += g_partq[p][c]; }
    float mean = s * invn;
    float var = q * invn - mean * mean;
    float sc = gamma[c] * rsqrtf(var + 1e-5f);
    g_scale[c] = sc;
    g_shift[c] = beta[c] - mean * sc;
}

__global__ void k_out(const float* __restrict__ x, float* __restrict__ out, int n) {
    int i = blockIdx.x * blockDim.x + threadIdx.x;
    if (i >= n * 128) return;
    int c4 = i & 127;
    float4 h = ((const float4*)g_h2)[i];
    float4 xv = ((const float4*)x)[i];
    float4 sc = ((const float4*)g_scale)[c4];
    float4 sh = ((const float4*)g_shift)[c4];
    float4 o;
    o.x = h.x * sc.x + sh.x + xv.x;
    o.y = h.y * sc.y + sh.y + xv.y;
    o.z = h.z * sc.z + sh.z + xv.z;
    o.w = h.w * sc.w + sh.w + xv.w;
    ((float4*)out)[i] = o;
}

// ---------------------------------------------------------------------------
extern "C" void kernel_launch(void* const* d_in, const int* in_sizes, int n_in,
                              void* d_out, int out_size) {
    const float* x     = (const float*)d_in[0];
    const int*   ei    = (const int*)d_in[1];
    const float* W1    = (const float*)d_in[2];
    const float* b1    = (const float*)d_in[3];
    const float* W2    = (const float*)d_in[4];
    const float* b2    = (const float*)d_in[5];
    const float* gamma = (const float*)d_in[6];
    const float* beta  = (const float*)d_in[7];
    float* out = (float*)d_out;

    int n = in_sizes[0] / DIM;
    int e = in_sizes[1] / 2;
    const int* src = ei;
    const int* dst = ei + e;

    static bool attr_set = false;
    if (!attr_set) {
        cudaFuncSetAttribute(k_gemm<1>, cudaFuncAttributeMaxDynamicSharedMemorySize, GEMM_SMEM);
        cudaFuncSetAttribute(k_gemm<0>, cudaFuncAttributeMaxDynamicSharedMemorySize, GEMM_SMEM);
        attr_set = true;
    }

    k_wconv<<<(DIM * DIM + 255) / 256, 256>>>(W1, W2, n);
    k_hist<<<(e + 255) / 256, 256>>>(dst, e);
    k_scan<<<1, 1024>>>(n);
    k_fill<<<(e + 255) / 256, 256>>>(src, dst, e);
    k_agg<<<n, 128>>>(x, n);

    int gy = (n + 127) / 128;               // 79
    dim3 gg(4, gy);
    k_gemm<1><<<gg, 256, GEMM_SMEM>>>(b1, n);
    k_gemm<0><<<gg, 256, GEMM_SMEM>>>(b2, n);

    k_bnparam<<<2, 256>>>(gamma, beta, 1.0f / (float)n, gy);
    k_out<<<(n * 128 + 255) / 256, 256>>>(x, out, n);
}